// round 2
// baseline (speedup 1.0000x reference)
#include <cuda_runtime.h>
#include <math.h>

#define N_NODES 200000
#define N_EDGES 800000
#define N_GRAPHS 8192
#define NFEAT 74
#define FPDIM 1024
#define HH 4
#define FF 50
#define HF 200
#define NT 16
#define GT 8

// ---------------- scratch (device globals; no allocation allowed) ------------
__device__ float g_feat[N_NODES * HF];   // feat = x @ W   (per layer, reused)
__device__ float g_x1[N_NODES * HF];     // layer-1 accumulator -> activated x1
__device__ float g_agg2[N_NODES * HF];   // layer-2 accumulator
__device__ float g_el[N_NODES * HH];
__device__ float g_er[N_NODES * HH];
__device__ float g_m[N_NODES * HH];      // segment max
__device__ float g_dn[N_NODES * HH];     // segment sum (denominator)
__device__ float g_ebuf[N_EDGES * HH];   // e, then overwritten with a=exp(e-m)
__device__ float g_pool[N_GRAPHS * FF];
__device__ float g_z1[N_GRAPHS * 128];

__device__ __forceinline__ float lrelu(float x, float s) { return x > 0.f ? x : s * x; }

// float atomic max via integer reinterpretation (monotone for +, reversed for -)
__device__ __forceinline__ void atomicMaxF(float* addr, float v) {
    if (v >= 0.f) atomicMax((int*)addr, __float_as_int(v));
    else          atomicMin((unsigned int*)addr, __float_as_uint(v));
}

__global__ void k_fill(float* p, float v, int n) {
    int i = blockIdx.x * blockDim.x + threadIdx.x;
    if (i < n) p[i] = v;
}

// ---------------- GAT layer 1 feature GEMM: feat = h@W1, x1 = h@resW1 + b1 ---
__global__ void k_feat1(const float* __restrict__ h, const float* __restrict__ W1,
                        const float* __restrict__ resW1, const float* __restrict__ al,
                        const float* __restrict__ ar, const float* __restrict__ b1) {
    __shared__ float sh[NT * NFEAT];
    __shared__ float sel[NT * HH], ser[NT * HH];
    int base = blockIdx.x * NT;
    for (int i = threadIdx.x; i < NT * NFEAT; i += blockDim.x)
        sh[i] = h[base * NFEAT + i];
    for (int i = threadIdx.x; i < NT * HH; i += blockDim.x) { sel[i] = 0.f; ser[i] = 0.f; }
    __syncthreads();
    for (int idx = threadIdx.x; idx < NT * HF; idx += blockDim.x) {
        int r = idx / HF, c = idx % HF;
        const float* hr = sh + r * NFEAT;
        float aF = 0.f, aR = 0.f;
#pragma unroll
        for (int k = 0; k < NFEAT; k++) {
            float hv = hr[k];
            aF = fmaf(hv, W1[k * HF + c], aF);
            aR = fmaf(hv, resW1[k * HF + c], aR);
        }
        int n = base + r;
        g_feat[n * HF + c] = aF;
        g_x1[n * HF + c] = aR + b1[c];
        int hd = c / FF, f = c % FF;
        atomicAdd(&sel[r * HH + hd], aF * al[hd * FF + f]);
        atomicAdd(&ser[r * HH + hd], aF * ar[hd * FF + f]);
    }
    __syncthreads();
    for (int i = threadIdx.x; i < NT * HH; i += blockDim.x) {
        g_el[base * HH + i] = sel[i];
        g_er[base * HH + i] = ser[i];
    }
}

// ---------------- GAT layer 2 feature GEMM: feat = x1@W2, agg2 = x1 + b2 -----
__global__ void k_feat2(const float* __restrict__ W2, const float* __restrict__ al,
                        const float* __restrict__ ar, const float* __restrict__ b2) {
    __shared__ float sh[NT * HF];
    __shared__ float sel[NT * HH], ser[NT * HH];
    int base = blockIdx.x * NT;
    for (int i = threadIdx.x; i < NT * HF; i += blockDim.x)
        sh[i] = g_x1[base * HF + i];
    for (int i = threadIdx.x; i < NT * HH; i += blockDim.x) { sel[i] = 0.f; ser[i] = 0.f; }
    __syncthreads();
    for (int idx = threadIdx.x; idx < NT * HF; idx += blockDim.x) {
        int r = idx / HF, c = idx % HF;
        const float* xr = sh + r * HF;
        float aF = 0.f;
#pragma unroll 8
        for (int k = 0; k < HF; k++)
            aF = fmaf(xr[k], W2[k * HF + c], aF);
        int n = base + r;
        g_feat[n * HF + c] = aF;
        g_agg2[n * HF + c] = xr[c] + b2[c];   // identity residual + bias
        int hd = c / FF, f = c % FF;
        atomicAdd(&sel[r * HH + hd], aF * al[hd * FF + f]);
        atomicAdd(&ser[r * HH + hd], aF * ar[hd * FF + f]);
    }
    __syncthreads();
    for (int i = threadIdx.x; i < NT * HH; i += blockDim.x) {
        g_el[base * HH + i] = sel[i];
        g_er[base * HH + i] = ser[i];
    }
}

// ---------------- edge passes ------------------------------------------------
__global__ void k_edge_max(const int* __restrict__ src, const int* __restrict__ dst) {
    int e = blockIdx.x * blockDim.x + threadIdx.x;
    if (e >= N_EDGES) return;
    int s = src[e], d = dst[e];
    float4 l4 = *(const float4*)(g_el + s * HH);
    float4 r4 = *(const float4*)(g_er + d * HH);
    float4 ev;
    ev.x = lrelu(l4.x + r4.x, 0.2f);
    ev.y = lrelu(l4.y + r4.y, 0.2f);
    ev.z = lrelu(l4.z + r4.z, 0.2f);
    ev.w = lrelu(l4.w + r4.w, 0.2f);
    *(float4*)(g_ebuf + e * HH) = ev;
    atomicMaxF(&g_m[d * HH + 0], ev.x);
    atomicMaxF(&g_m[d * HH + 1], ev.y);
    atomicMaxF(&g_m[d * HH + 2], ev.z);
    atomicMaxF(&g_m[d * HH + 3], ev.w);
}

__global__ void k_edge_sum(const int* __restrict__ dst) {
    int e = blockIdx.x * blockDim.x + threadIdx.x;
    if (e >= N_EDGES) return;
    int d = dst[e];
    float4 ev = *(const float4*)(g_ebuf + e * HH);
    float4 mv = *(const float4*)(g_m + d * HH);
    float4 av;
    av.x = __expf(ev.x - mv.x);
    av.y = __expf(ev.y - mv.y);
    av.z = __expf(ev.z - mv.z);
    av.w = __expf(ev.w - mv.w);
    *(float4*)(g_ebuf + e * HH) = av;
    atomicAdd(&g_dn[d * HH + 0], av.x);
    atomicAdd(&g_dn[d * HH + 1], av.y);
    atomicAdd(&g_dn[d * HH + 2], av.z);
    atomicAdd(&g_dn[d * HH + 3], av.w);
}

// one warp per edge: acc[dst, :] += alpha[h] * feat[src, :]
__global__ void k_edge_agg(const int* __restrict__ src, const int* __restrict__ dst,
                           float* __restrict__ acc) {
    int gt = blockIdx.x * blockDim.x + threadIdx.x;
    int e = gt >> 5, lane = gt & 31;
    if (e >= N_EDGES) return;
    int s = src[e], d = dst[e];
    float4 a4 = *(const float4*)(g_ebuf + e * HH);
    float4 d4 = *(const float4*)(g_dn + d * HH);
    float w0 = a4.x / d4.x, w1 = a4.y / d4.y, w2 = a4.z / d4.z, w3 = a4.w / d4.w;
    const float* fs = g_feat + s * HF;
    float* xd = acc + d * HF;
#pragma unroll
    for (int t = 0; t < 7; t++) {
        int j = lane + t * 32;
        if (j < HF) {
            float w = (j < FF) ? w0 : (j < 2 * FF) ? w1 : (j < 3 * FF) ? w2 : w3;
            atomicAdd(&xd[j], w * fs[j]);
        }
    }
}

__global__ void k_act1() {
    int i = blockIdx.x * blockDim.x + threadIdx.x;
    if (i < N_NODES * HF) {
        float v = g_x1[i];
        g_x1[i] = v > 0.f ? v : 0.01f * v;
    }
}

// ---------------- head-mean + per-graph max pool -----------------------------
__global__ void k_pool(const int* __restrict__ gid) {
    int i = blockIdx.x * blockDim.x + threadIdx.x;
    if (i >= N_NODES * FF) return;
    int n = i / FF, f = i - n * FF;
    const float* r = g_agg2 + n * HF;
    float v = 0.25f * (r[f] + r[FF + f] + r[2 * FF + f] + r[3 * FF + f]);
    atomicMaxF(&g_pool[gid[n] * FF + f], v);
}

// ---------------- MLP layer 1 + BN (eval mode) -------------------------------
__global__ void k_mlp1(const float* __restrict__ fps, const float* __restrict__ lw1,
                       const float* __restrict__ lb1, const float* __restrict__ bn_g,
                       const float* __restrict__ bn_b, const float* __restrict__ bn_rm,
                       const float* __restrict__ bn_rv) {
    __shared__ float sz[GT * 1074];
    int gb = blockIdx.x * GT;
    for (int i = threadIdx.x; i < GT * FF; i += blockDim.x) {
        int r = i / FF, k = i % FF;
        sz[r * 1074 + k] = g_pool[(gb + r) * FF + k];
    }
    for (int i = threadIdx.x; i < GT * FPDIM; i += blockDim.x) {
        int r = i / FPDIM, k = i % FPDIM;
        sz[r * 1074 + FF + k] = fps[(gb + r) * FPDIM + k];
    }
    __syncthreads();
    int c = threadIdx.x;  // blockDim = 128
    float acc[GT];
#pragma unroll
    for (int r = 0; r < GT; r++) acc[r] = 0.f;
    for (int k = 0; k < 1074; k++) {
        float w = lw1[k * 128 + c];
#pragma unroll
        for (int r = 0; r < GT; r++) acc[r] = fmaf(sz[r * 1074 + k], w, acc[r]);
    }
    float lb = lb1[c];
    float mu = bn_rm[c];
    float scl = rsqrtf(bn_rv[c] + 1e-5f) * bn_g[c];
    float bb = bn_b[c];
#pragma unroll
    for (int r = 0; r < GT; r++) {
        float z = fmaxf(acc[r] + lb, 0.f);
        g_z1[(gb + r) * 128 + c] = (z - mu) * scl + bb;
    }
}

// ---------------- MLP layer 2 + capsule head ---------------------------------
__global__ void k_mlp2caps(const float* __restrict__ lw2, const float* __restrict__ lb2,
                           const float* __restrict__ capsW, const float* __restrict__ capsB,
                           float* __restrict__ out) {
    __shared__ float sz1[128];
    __shared__ float sz2[128];
    __shared__ float su[16 * 8];
    __shared__ float suh[2 * 16 * 2];
    __shared__ float sUS[4];
    __shared__ float sas[2 * 16];
    __shared__ float scx[2 * 16];
    __shared__ float ss[4];
    int g = blockIdx.x;
    int t = threadIdx.x;
    sz1[t] = g_z1[g * 128 + t];
    __syncthreads();
    float acc = lb2[t];
#pragma unroll 8
    for (int k = 0; k < 128; k++) acc = fmaf(sz1[k], lw2[k * 128 + t], acc);
    sz2[t] = fmaxf(acc, 0.f);
    __syncthreads();
    if (t < 16) {  // squash over rows of 8
        float sq = 0.f;
#pragma unroll
        for (int e = 0; e < 8; e++) { float v = sz2[t * 8 + e]; sq += v * v; }
        float rt = sqrtf(sq);
        float f = (1.f - __expf(-rt)) / sqrtf(sq + 1e-8f);
#pragma unroll
        for (int e = 0; e < 8; e++) su[t * 8 + e] = f * sz2[t * 8 + e];
    }
    __syncthreads();
    if (t < 64) {  // u_hat[n,c,d]
        int n = t >> 5, rem = t & 31, c = rem >> 1, d = rem & 1;
        const float* w = capsW + ((n * 16 + c) * 2 + d) * 8;
        float s = 0.f;
#pragma unroll
        for (int e = 0; e < 8; e++) s = fmaf(w[e], su[c * 8 + e], s);
        suh[(n * 16 + c) * 2 + d] = s;
    }
    __syncthreads();
    if (t < 4) {  // US[n,d] = sum_c u_hat[n,c,d]
        int n = t >> 1, d = t & 1;
        float s = 0.f;
        for (int c = 0; c < 16; c++) s += suh[(n * 16 + c) * 2 + d];
        sUS[t] = s;
    }
    __syncthreads();
    if (t < 32) {  // asum[n,k] = coef * sum_d US[n,d]*u_hat[n,k,d]
        int n = t >> 4, k = t & 15;
        sas[t] = 0.08838834764831845f *
                 (sUS[n * 2 + 0] * suh[(n * 16 + k) * 2 + 0] +
                  sUS[n * 2 + 1] * suh[(n * 16 + k) * 2 + 1]);
    }
    __syncthreads();
    if (t < 16) {  // softmax over n (2 values) per k
        float a0 = sas[t], a1 = sas[16 + t];
        float m = fmaxf(a0, a1);
        float e0 = __expf(a0 - m), e1 = __expf(a1 - m);
        float inv = 1.f / (e0 + e1);
        scx[t] = e0 * inv;
        scx[16 + t] = e1 * inv;
    }
    __syncthreads();
    if (t < 4) {  // s[n,d] = sum_k (c+B)[n,k]*u_hat[n,k,d]
        int n = t >> 1, d = t & 1;
        float s = 0.f;
        for (int k = 0; k < 16; k++)
            s = fmaf(scx[n * 16 + k] + capsB[n * 16 + k], suh[(n * 16 + k) * 2 + d], s);
        ss[n * 2 + d] = s;
    }
    __syncthreads();
    if (t < 2) {  // v = squash(s); out = ||v||
        float s0 = ss[t * 2 + 0], s1 = ss[t * 2 + 1];
        float sq = s0 * s0 + s1 * s1;
        float rt = sqrtf(sq);
        float f = (1.f - __expf(-rt)) / sqrtf(sq + 1e-8f);
        float v0 = f * s0, v1 = f * s1;
        out[g * 2 + t] = sqrtf(v0 * v0 + v1 * v1 + 1e-8f);
    }
}

// ---------------- launcher ---------------------------------------------------
extern "C" void kernel_launch(void* const* d_in, const int* in_sizes, int n_in,
                              void* d_out, int out_size) {
    const float* h     = (const float*)d_in[0];
    const float* fps   = (const float*)d_in[1];
    const int*   src   = (const int*)d_in[2];
    const int*   dst   = (const int*)d_in[3];
    const int*   gid   = (const int*)d_in[4];
    const float* W1    = (const float*)d_in[5];
    const float* al1   = (const float*)d_in[6];
    const float* ar1   = (const float*)d_in[7];
    const float* b1    = (const float*)d_in[8];
    const float* resW1 = (const float*)d_in[9];
    const float* W2    = (const float*)d_in[10];
    const float* al2   = (const float*)d_in[11];
    const float* ar2   = (const float*)d_in[12];
    const float* b2    = (const float*)d_in[13];
    const float* lw1   = (const float*)d_in[14];
    const float* lb1   = (const float*)d_in[15];
    const float* bn_g  = (const float*)d_in[16];
    const float* bn_b  = (const float*)d_in[17];
    const float* bn_rm = (const float*)d_in[18];
    const float* bn_rv = (const float*)d_in[19];
    const float* lw2   = (const float*)d_in[20];
    const float* lb2   = (const float*)d_in[21];
    const float* capsW = (const float*)d_in[22];
    const float* capsB = (const float*)d_in[23];
    float* out = (float*)d_out;

    float *p_m, *p_dn, *p_x1, *p_agg2, *p_pool;
    cudaGetSymbolAddress((void**)&p_m, g_m);
    cudaGetSymbolAddress((void**)&p_dn, g_dn);
    cudaGetSymbolAddress((void**)&p_x1, g_x1);
    cudaGetSymbolAddress((void**)&p_agg2, g_agg2);
    cudaGetSymbolAddress((void**)&p_pool, g_pool);

    const int NB_N4 = (N_NODES * HH + 255) / 256;
    const int NB_E  = (N_EDGES + 255) / 256;
    const int NB_EW = (N_EDGES * 32 + 255) / 256;

    // ---- GAT layer 1 ----
    k_fill<<<NB_N4, 256>>>(p_m, -INFINITY, N_NODES * HH);
    k_fill<<<NB_N4, 256>>>(p_dn, 0.f, N_NODES * HH);
    k_feat1<<<N_NODES / NT, 256>>>(h, W1, resW1, al1, ar1, b1);
    k_edge_max<<<NB_E, 256>>>(src, dst);
    k_edge_sum<<<NB_E, 256>>>(dst);
    k_edge_agg<<<NB_EW, 256>>>(src, dst, p_x1);
    k_act1<<<(N_NODES * HF + 255) / 256, 256>>>();

    // ---- GAT layer 2 ----
    k_fill<<<NB_N4, 256>>>(p_m, -INFINITY, N_NODES * HH);
    k_fill<<<NB_N4, 256>>>(p_dn, 0.f, N_NODES * HH);
    k_feat2<<<N_NODES / NT, 256>>>(W2, al2, ar2, b2);
    k_edge_max<<<NB_E, 256>>>(src, dst);
    k_edge_sum<<<NB_E, 256>>>(dst);
    k_edge_agg<<<NB_EW, 256>>>(src, dst, p_agg2);

    // ---- pool + MLP + caps ----
    k_fill<<<(N_GRAPHS * FF + 255) / 256, 256>>>(p_pool, -INFINITY, N_GRAPHS * FF);
    k_pool<<<(N_NODES * FF + 255) / 256, 256>>>(gid);
    k_mlp1<<<N_GRAPHS / GT, 128>>>(fps, lw1, lb1, bn_g, bn_b, bn_rm, bn_rv);
    k_mlp2caps<<<N_GRAPHS, 128>>>(lw2, lb2, capsW, capsB, out);
}

// round 3
// speedup vs baseline: 1.4563x; 1.4563x over previous
#include <cuda_runtime.h>
#include <math.h>

#define N_NODES 200000
#define N_EDGES 800000
#define N_GRAPHS 8192
#define NFEAT 74
#define FPDIM 1024
#define HH 4
#define FF 50
#define HF 200
#define NT 16
#define GT 8

// ---------------- scratch ----------------------------------------------------
__device__ float g_feat[N_NODES * HF];
__device__ float g_x1[N_NODES * HF];      // res+bias, then layer-1 output
__device__ float g_el[N_NODES * HH];
__device__ float g_er[N_NODES * HH];
__device__ float g_pool[N_GRAPHS * FF];
__device__ float g_z1[N_GRAPHS * 128];
__device__ int   g_deg[N_NODES];
__device__ int   g_cnt[N_NODES];
__device__ int   g_rowptr[N_NODES + 1];
__device__ int   g_csrc[N_EDGES];
__device__ int   g_bsum[256];
__device__ int   g_boff[256];

__device__ __forceinline__ float lrelu(float x, float s) { return x > 0.f ? x : s * x; }

__device__ __forceinline__ void atomicMaxF(float* addr, float v) {
    if (v >= 0.f) atomicMax((int*)addr, __float_as_int(v));
    else          atomicMin((unsigned int*)addr, __float_as_uint(v));
}

__device__ __forceinline__ float pickw(float4 a, int h) {
    return h == 0 ? a.x : (h == 1 ? a.y : (h == 2 ? a.z : a.w));
}

__global__ void k_fill(float* p, float v, int n) {
    int i = blockIdx.x * blockDim.x + threadIdx.x;
    if (i < n) p[i] = v;
}

// ---------------- CSR build --------------------------------------------------
__global__ void k_deg(const int* __restrict__ dst) {
    int e = blockIdx.x * blockDim.x + threadIdx.x;
    if (e < N_EDGES) atomicAdd(&g_deg[dst[e]], 1);
}

__global__ void k_scan1() {
    int i = blockIdx.x * 1024 + threadIdx.x;
    int v = (i < N_NODES) ? g_deg[i] : 0;
    int lane = threadIdx.x & 31, wid = threadIdx.x >> 5;
    int x = v;
#pragma unroll
    for (int o = 1; o < 32; o <<= 1) {
        int y = __shfl_up_sync(~0u, x, o);
        if (lane >= o) x += y;
    }
    __shared__ int ws[32];
    if (lane == 31) ws[wid] = x;
    __syncthreads();
    if (wid == 0) {
        int w = ws[lane];
#pragma unroll
        for (int o = 1; o < 32; o <<= 1) {
            int y = __shfl_up_sync(~0u, w, o);
            if (lane >= o) w += y;
        }
        ws[lane] = w;
    }
    __syncthreads();
    int incl = x + (wid > 0 ? ws[wid - 1] : 0);
    if (i < N_NODES) g_rowptr[i + 1] = incl;
    if (threadIdx.x == 1023) g_bsum[blockIdx.x] = incl;
}

__global__ void k_scan2(int nb) {
    int lane = threadIdx.x & 31, wid = threadIdx.x >> 5;
    int v = (threadIdx.x < nb) ? g_bsum[threadIdx.x] : 0;
    int x = v;
#pragma unroll
    for (int o = 1; o < 32; o <<= 1) {
        int y = __shfl_up_sync(~0u, x, o);
        if (lane >= o) x += y;
    }
    __shared__ int ws[8];
    if (lane == 31) ws[wid] = x;
    __syncthreads();
    if (threadIdx.x < 8) {
        int w = ws[threadIdx.x];
#pragma unroll
        for (int o = 1; o < 8; o <<= 1) {
            int y = __shfl_up_sync(0xffu, w, o);
            if ((threadIdx.x & 7) >= o) w += y;
        }
        ws[threadIdx.x] = w;
    }
    __syncthreads();
    int incl = x + (wid > 0 ? ws[wid - 1] : 0);
    g_boff[threadIdx.x] = incl - v;   // exclusive
}

__global__ void k_scan3() {
    int i = blockIdx.x * blockDim.x + threadIdx.x;
    if (i < N_NODES) g_rowptr[i + 1] += g_boff[i >> 10];
    if (i == 0) g_rowptr[0] = 0;
}

__global__ void k_scatter(const int* __restrict__ src, const int* __restrict__ dst) {
    int e = blockIdx.x * blockDim.x + threadIdx.x;
    if (e >= N_EDGES) return;
    int d = dst[e];
    int r = atomicAdd(&g_cnt[d], 1);
    g_csrc[g_rowptr[d] + r] = src[e];
}

// ---------------- layer-1 GEMM: feat=h@W1, x1=h@resW1+b1, el/er --------------
__global__ void __launch_bounds__(224) k_feat1(
        const float* __restrict__ h, const float* __restrict__ W1,
        const float* __restrict__ resW1, const float* __restrict__ al,
        const float* __restrict__ ar, const float* __restrict__ b1) {
    __shared__ float sxT[NFEAT * NT];          // [k][r]
    __shared__ float sel[NT * HH], ser[NT * HH];
    int base = blockIdx.x * NT;
    int t = threadIdx.x;
    for (int i = t; i < NT * NFEAT; i += 224) {
        int r = i / NFEAT, k = i - r * NFEAT;
        sxT[k * NT + r] = h[(base + r) * NFEAT + k];
    }
    for (int i = t; i < NT * HH; i += 224) { sel[i] = 0.f; ser[i] = 0.f; }
    __syncthreads();
    int c = t;
    if (c < HF) {
        float aF[NT], aR[NT];
#pragma unroll
        for (int r = 0; r < NT; r++) { aF[r] = 0.f; aR[r] = 0.f; }
#pragma unroll 2
        for (int k = 0; k < NFEAT; k++) {
            float w1v = W1[k * HF + c];
            float wrv = resW1[k * HF + c];
            const float4* xk = (const float4*)(sxT + k * NT);
#pragma unroll
            for (int q = 0; q < NT / 4; q++) {
                float4 xv = xk[q];
                aF[4 * q + 0] = fmaf(xv.x, w1v, aF[4 * q + 0]);
                aF[4 * q + 1] = fmaf(xv.y, w1v, aF[4 * q + 1]);
                aF[4 * q + 2] = fmaf(xv.z, w1v, aF[4 * q + 2]);
                aF[4 * q + 3] = fmaf(xv.w, w1v, aF[4 * q + 3]);
                aR[4 * q + 0] = fmaf(xv.x, wrv, aR[4 * q + 0]);
                aR[4 * q + 1] = fmaf(xv.y, wrv, aR[4 * q + 1]);
                aR[4 * q + 2] = fmaf(xv.z, wrv, aR[4 * q + 2]);
                aR[4 * q + 3] = fmaf(xv.w, wrv, aR[4 * q + 3]);
            }
        }
        float alc = al[c], arc = ar[c], b1c = b1[c];
        int hd = c / FF;
#pragma unroll
        for (int r = 0; r < NT; r++) {
            g_feat[(base + r) * HF + c] = aF[r];
            g_x1[(base + r) * HF + c] = aR[r] + b1c;
            atomicAdd(&sel[r * HH + hd], aF[r] * alc);
            atomicAdd(&ser[r * HH + hd], aF[r] * arc);
        }
    }
    __syncthreads();
    for (int i = t; i < NT * HH; i += 224) {
        g_el[base * HH + i] = sel[i];
        g_er[base * HH + i] = ser[i];
    }
}

// ---------------- layer-2 GEMM: feat=x1@W2, el/er ----------------------------
__global__ void __launch_bounds__(224) k_feat2(
        const float* __restrict__ W2, const float* __restrict__ al,
        const float* __restrict__ ar) {
    __shared__ float sxT[HF * NT];             // [k][r]  12.8 KB
    __shared__ float sel[NT * HH], ser[NT * HH];
    int base = blockIdx.x * NT;
    int t = threadIdx.x;
    for (int i = t; i < NT * HF; i += 224) {
        int r = i / HF, k = i - r * HF;
        sxT[k * NT + r] = g_x1[(base + r) * HF + k];
    }
    for (int i = t; i < NT * HH; i += 224) { sel[i] = 0.f; ser[i] = 0.f; }
    __syncthreads();
    int c = t;
    if (c < HF) {
        float aF[NT];
#pragma unroll
        for (int r = 0; r < NT; r++) aF[r] = 0.f;
#pragma unroll 2
        for (int k = 0; k < HF; k++) {
            float wv = W2[k * HF + c];
            const float4* xk = (const float4*)(sxT + k * NT);
#pragma unroll
            for (int q = 0; q < NT / 4; q++) {
                float4 xv = xk[q];
                aF[4 * q + 0] = fmaf(xv.x, wv, aF[4 * q + 0]);
                aF[4 * q + 1] = fmaf(xv.y, wv, aF[4 * q + 1]);
                aF[4 * q + 2] = fmaf(xv.z, wv, aF[4 * q + 2]);
                aF[4 * q + 3] = fmaf(xv.w, wv, aF[4 * q + 3]);
            }
        }
        float alc = al[c], arc = ar[c];
        int hd = c / FF;
#pragma unroll
        for (int r = 0; r < NT; r++) {
            g_feat[(base + r) * HF + c] = aF[r];
            atomicAdd(&sel[r * HH + hd], aF[r] * alc);
            atomicAdd(&ser[r * HH + hd], aF[r] * arc);
        }
    }
    __syncthreads();
    for (int i = t; i < NT * HH; i += 224) {
        g_el[base * HH + i] = sel[i];
        g_er[base * HH + i] = ser[i];
    }
}

// ------- fused per-node softmax + aggregation + epilogue (warp per node) -----
template <int LAYER>
__global__ void __launch_bounds__(128) k_agg(const int* __restrict__ gid,
                                             const float* __restrict__ b2) {
    __shared__ float sm[4][HF];
    int w = threadIdx.x >> 5, lane = threadIdx.x & 31;
    int n = blockIdx.x * 4 + w;
    int beg = g_rowptr[n], deg = g_rowptr[n + 1] - beg;
    float4 er4 = *(const float4*)(g_er + n * 4);
    float4 m4 = make_float4(-INFINITY, -INFINITY, -INFINITY, -INFINITY);
    float4 dn4 = make_float4(0.f, 0.f, 0.f, 0.f);
    float i0 = 0.f, i1 = 0.f, i2 = 0.f, i3 = 0.f;
    if (deg > 0) {
        for (int j = lane; j < deg; j += 32) {
            int s = g_csrc[beg + j];
            float4 l4 = *(const float4*)(g_el + s * 4);
            m4.x = fmaxf(m4.x, lrelu(l4.x + er4.x, 0.2f));
            m4.y = fmaxf(m4.y, lrelu(l4.y + er4.y, 0.2f));
            m4.z = fmaxf(m4.z, lrelu(l4.z + er4.z, 0.2f));
            m4.w = fmaxf(m4.w, lrelu(l4.w + er4.w, 0.2f));
        }
#pragma unroll
        for (int o = 16; o; o >>= 1) {
            m4.x = fmaxf(m4.x, __shfl_xor_sync(~0u, m4.x, o));
            m4.y = fmaxf(m4.y, __shfl_xor_sync(~0u, m4.y, o));
            m4.z = fmaxf(m4.z, __shfl_xor_sync(~0u, m4.z, o));
            m4.w = fmaxf(m4.w, __shfl_xor_sync(~0u, m4.w, o));
        }
        for (int j = lane; j < deg; j += 32) {
            int s = g_csrc[beg + j];
            float4 l4 = *(const float4*)(g_el + s * 4);
            dn4.x += __expf(lrelu(l4.x + er4.x, 0.2f) - m4.x);
            dn4.y += __expf(lrelu(l4.y + er4.y, 0.2f) - m4.y);
            dn4.z += __expf(lrelu(l4.z + er4.z, 0.2f) - m4.z);
            dn4.w += __expf(lrelu(l4.w + er4.w, 0.2f) - m4.w);
        }
#pragma unroll
        for (int o = 16; o; o >>= 1) {
            dn4.x += __shfl_xor_sync(~0u, dn4.x, o);
            dn4.y += __shfl_xor_sync(~0u, dn4.y, o);
            dn4.z += __shfl_xor_sync(~0u, dn4.z, o);
            dn4.w += __shfl_xor_sync(~0u, dn4.w, o);
        }
        i0 = 1.f / dn4.x; i1 = 1.f / dn4.y; i2 = 1.f / dn4.z; i3 = 1.f / dn4.w;
    }
    // per-lane head mapping: slot0 cols [4*lane, +3], slot1 cols [128+4*lane, +3]
    int c0 = 4 * lane, c1 = 128 + 4 * lane;
    int h0l = c0 / FF, h0h = (c0 + 3) / FF, n0 = (h0l == h0h) ? 4 : (FF * h0h - c0);
    int h1l = c1 / FF, h1h = (c1 + 3) / FF, n1 = (h1l == h1h) ? 4 : (FF * h1h - c1);
    float4 acc0 = make_float4(0.f, 0.f, 0.f, 0.f);
    float4 acc1 = make_float4(0.f, 0.f, 0.f, 0.f);
    for (int j = 0; j < deg; j++) {
        int s = g_csrc[beg + j];
        float4 l4 = *(const float4*)(g_el + s * 4);
        float4 aj;
        aj.x = __expf(lrelu(l4.x + er4.x, 0.2f) - m4.x) * i0;
        aj.y = __expf(lrelu(l4.y + er4.y, 0.2f) - m4.y) * i1;
        aj.z = __expf(lrelu(l4.z + er4.z, 0.2f) - m4.z) * i2;
        aj.w = __expf(lrelu(l4.w + er4.w, 0.2f) - m4.w) * i3;
        const float4* fr = (const float4*)(g_feat + s * HF);
        float4 f0 = fr[lane];
        float wl = pickw(aj, h0l), wh = pickw(aj, h0h);
        acc0.x = fmaf((0 < n0 ? wl : wh), f0.x, acc0.x);
        acc0.y = fmaf((1 < n0 ? wl : wh), f0.y, acc0.y);
        acc0.z = fmaf((2 < n0 ? wl : wh), f0.z, acc0.z);
        acc0.w = fmaf((3 < n0 ? wl : wh), f0.w, acc0.w);
        if (lane < 18) {
            float4 f1 = fr[32 + lane];
            float wl1 = pickw(aj, h1l), wh1 = pickw(aj, h1h);
            acc1.x = fmaf((0 < n1 ? wl1 : wh1), f1.x, acc1.x);
            acc1.y = fmaf((1 < n1 ? wl1 : wh1), f1.y, acc1.y);
            acc1.z = fmaf((2 < n1 ? wl1 : wh1), f1.z, acc1.z);
            acc1.w = fmaf((3 < n1 ? wl1 : wh1), f1.w, acc1.w);
        }
    }
    float4* xrow = (float4*)(g_x1 + n * HF);
    if (LAYER == 1) {
        float4 r0 = xrow[lane];
        r0.x = lrelu(acc0.x + r0.x, 0.01f);
        r0.y = lrelu(acc0.y + r0.y, 0.01f);
        r0.z = lrelu(acc0.z + r0.z, 0.01f);
        r0.w = lrelu(acc0.w + r0.w, 0.01f);
        xrow[lane] = r0;
        if (lane < 18) {
            float4 r1 = xrow[32 + lane];
            r1.x = lrelu(acc1.x + r1.x, 0.01f);
            r1.y = lrelu(acc1.y + r1.y, 0.01f);
            r1.z = lrelu(acc1.z + r1.z, 0.01f);
            r1.w = lrelu(acc1.w + r1.w, 0.01f);
            xrow[32 + lane] = r1;
        }
    } else {
        float4 r0 = xrow[lane];
        float4 bb0 = *(const float4*)(b2 + c0);
        sm[w][c0 + 0] = acc0.x + r0.x + bb0.x;
        sm[w][c0 + 1] = acc0.y + r0.y + bb0.y;
        sm[w][c0 + 2] = acc0.z + r0.z + bb0.z;
        sm[w][c0 + 3] = acc0.w + r0.w + bb0.w;
        if (lane < 18) {
            float4 r1 = xrow[32 + lane];
            float4 bb1 = *(const float4*)(b2 + c1);
            sm[w][c1 + 0] = acc1.x + r1.x + bb1.x;
            sm[w][c1 + 1] = acc1.y + r1.y + bb1.y;
            sm[w][c1 + 2] = acc1.z + r1.z + bb1.z;
            sm[w][c1 + 3] = acc1.w + r1.w + bb1.w;
        }
        __syncwarp();
        int g = gid[n];
        {
            int f = lane;   // 0..31 < 50
            float v = 0.25f * (sm[w][f] + sm[w][f + FF] + sm[w][f + 2 * FF] + sm[w][f + 3 * FF]);
            atomicMaxF(&g_pool[g * FF + f], v);
        }
        if (lane < 18) {
            int f = 32 + lane;
            float v = 0.25f * (sm[w][f] + sm[w][f + FF] + sm[w][f + 2 * FF] + sm[w][f + 3 * FF]);
            atomicMaxF(&g_pool[g * FF + f], v);
        }
    }
}

// ---------------- MLP layer 1 + BN -------------------------------------------
__global__ void k_mlp1(const float* __restrict__ fps, const float* __restrict__ lw1,
                       const float* __restrict__ lb1, const float* __restrict__ bn_g,
                       const float* __restrict__ bn_b, const float* __restrict__ bn_rm,
                       const float* __restrict__ bn_rv) {
    __shared__ float sz[GT * 1074];
    int gb = blockIdx.x * GT;
    for (int i = threadIdx.x; i < GT * FF; i += blockDim.x) {
        int r = i / FF, k = i % FF;
        sz[r * 1074 + k] = g_pool[(gb + r) * FF + k];
    }
    for (int i = threadIdx.x; i < GT * FPDIM; i += blockDim.x) {
        int r = i / FPDIM, k = i % FPDIM;
        sz[r * 1074 + FF + k] = fps[(gb + r) * FPDIM + k];
    }
    __syncthreads();
    int c = threadIdx.x;
    float acc[GT];
#pragma unroll
    for (int r = 0; r < GT; r++) acc[r] = 0.f;
    for (int k = 0; k < 1074; k++) {
        float w = lw1[k * 128 + c];
#pragma unroll
        for (int r = 0; r < GT; r++) acc[r] = fmaf(sz[r * 1074 + k], w, acc[r]);
    }
    float lb = lb1[c];
    float mu = bn_rm[c];
    float scl = rsqrtf(bn_rv[c] + 1e-5f) * bn_g[c];
    float bb = bn_b[c];
#pragma unroll
    for (int r = 0; r < GT; r++) {
        float z = fmaxf(acc[r] + lb, 0.f);
        g_z1[(gb + r) * 128 + c] = (z - mu) * scl + bb;
    }
}

// ---------------- MLP layer 2 + capsule head ---------------------------------
__global__ void k_mlp2caps(const float* __restrict__ lw2, const float* __restrict__ lb2,
                           const float* __restrict__ capsW, const float* __restrict__ capsB,
                           float* __restrict__ out) {
    __shared__ float sz1[128];
    __shared__ float sz2[128];
    __shared__ float su[16 * 8];
    __shared__ float suh[2 * 16 * 2];
    __shared__ float sUS[4];
    __shared__ float sas[2 * 16];
    __shared__ float scx[2 * 16];
    __shared__ float ss[4];
    int g = blockIdx.x;
    int t = threadIdx.x;
    sz1[t] = g_z1[g * 128 + t];
    __syncthreads();
    float acc = lb2[t];
#pragma unroll 8
    for (int k = 0; k < 128; k++) acc = fmaf(sz1[k], lw2[k * 128 + t], acc);
    sz2[t] = fmaxf(acc, 0.f);
    __syncthreads();
    if (t < 16) {
        float sq = 0.f;
#pragma unroll
        for (int e = 0; e < 8; e++) { float v = sz2[t * 8 + e]; sq += v * v; }
        float rt = sqrtf(sq);
        float f = (1.f - __expf(-rt)) / sqrtf(sq + 1e-8f);
#pragma unroll
        for (int e = 0; e < 8; e++) su[t * 8 + e] = f * sz2[t * 8 + e];
    }
    __syncthreads();
    if (t < 64) {
        int n = t >> 5, rem = t & 31, c = rem >> 1, d = rem & 1;
        const float* w = capsW + ((n * 16 + c) * 2 + d) * 8;
        float s = 0.f;
#pragma unroll
        for (int e = 0; e < 8; e++) s = fmaf(w[e], su[c * 8 + e], s);
        suh[(n * 16 + c) * 2 + d] = s;
    }
    __syncthreads();
    if (t < 4) {
        int n = t >> 1, d = t & 1;
        float s = 0.f;
        for (int c = 0; c < 16; c++) s += suh[(n * 16 + c) * 2 + d];
        sUS[t] = s;
    }
    __syncthreads();
    if (t < 32) {
        int n = t >> 4, k = t & 15;
        sas[t] = 0.08838834764831845f *
                 (sUS[n * 2 + 0] * suh[(n * 16 + k) * 2 + 0] +
                  sUS[n * 2 + 1] * suh[(n * 16 + k) * 2 + 1]);
    }
    __syncthreads();
    if (t < 16) {
        float a0 = sas[t], a1 = sas[16 + t];
        float m = fmaxf(a0, a1);
        float e0 = __expf(a0 - m), e1 = __expf(a1 - m);
        float inv = 1.f / (e0 + e1);
        scx[t] = e0 * inv;
        scx[16 + t] = e1 * inv;
    }
    __syncthreads();
    if (t < 4) {
        int n = t >> 1, d = t & 1;
        float s = 0.f;
        for (int k = 0; k < 16; k++)
            s = fmaf(scx[n * 16 + k] + capsB[n * 16 + k], suh[(n * 16 + k) * 2 + d], s);
        ss[n * 2 + d] = s;
    }
    __syncthreads();
    if (t < 2) {
        float s0 = ss[t * 2 + 0], s1 = ss[t * 2 + 1];
        float sq = s0 * s0 + s1 * s1;
        float rt = sqrtf(sq);
        float f = (1.f - __expf(-rt)) / sqrtf(sq + 1e-8f);
        float v0 = f * s0, v1 = f * s1;
        out[g * 2 + t] = sqrtf(v0 * v0 + v1 * v1 + 1e-8f);
    }
}

// ---------------- launcher ---------------------------------------------------
extern "C" void kernel_launch(void* const* d_in, const int* in_sizes, int n_in,
                              void* d_out, int out_size) {
    const float* h     = (const float*)d_in[0];
    const float* fps   = (const float*)d_in[1];
    const int*   src   = (const int*)d_in[2];
    const int*   dst   = (const int*)d_in[3];
    const int*   gid   = (const int*)d_in[4];
    const float* W1    = (const float*)d_in[5];
    const float* al1   = (const float*)d_in[6];
    const float* ar1   = (const float*)d_in[7];
    const float* b1    = (const float*)d_in[8];
    const float* resW1 = (const float*)d_in[9];
    const float* W2    = (const float*)d_in[10];
    const float* al2   = (const float*)d_in[11];
    const float* ar2   = (const float*)d_in[12];
    const float* b2    = (const float*)d_in[13];
    const float* lw1   = (const float*)d_in[14];
    const float* lb1   = (const float*)d_in[15];
    const float* bn_g  = (const float*)d_in[16];
    const float* bn_b  = (const float*)d_in[17];
    const float* bn_rm = (const float*)d_in[18];
    const float* bn_rv = (const float*)d_in[19];
    const float* lw2   = (const float*)d_in[20];
    const float* lb2   = (const float*)d_in[21];
    const float* capsW = (const float*)d_in[22];
    const float* capsB = (const float*)d_in[23];
    float* out = (float*)d_out;

    float *p_deg, *p_cnt, *p_pool;
    cudaGetSymbolAddress((void**)&p_deg, g_deg);
    cudaGetSymbolAddress((void**)&p_cnt, g_cnt);
    cudaGetSymbolAddress((void**)&p_pool, g_pool);

    const int NB_E = (N_EDGES + 255) / 256;
    const int NB_N = (N_NODES + 255) / 256;
    const int NB_SCAN = (N_NODES + 1023) / 1024;   // 196

    // ---- CSR build (once; graph shared by both layers) ----
    k_fill<<<NB_N, 256>>>(p_deg, 0.f, N_NODES);
    k_fill<<<NB_N, 256>>>(p_cnt, 0.f, N_NODES);
    k_fill<<<(N_GRAPHS * FF + 255) / 256, 256>>>(p_pool, -INFINITY, N_GRAPHS * FF);
    k_deg<<<NB_E, 256>>>(dst);
    k_scan1<<<NB_SCAN, 1024>>>();
    k_scan2<<<1, 256>>>(NB_SCAN);
    k_scan3<<<NB_N, 256>>>();
    k_scatter<<<NB_E, 256>>>(src, dst);

    // ---- GAT layer 1 ----
    k_feat1<<<N_NODES / NT, 224>>>(h, W1, resW1, al1, ar1, b1);
    k_agg<1><<<N_NODES / 4, 128>>>(gid, b2);

    // ---- GAT layer 2 (+ fused head-mean + graph max-pool) ----
    k_feat2<<<N_NODES / NT, 224>>>(W2, al2, ar2);
    k_agg<2><<<N_NODES / 4, 128>>>(gid, b2);

    // ---- MLP + caps ----
    k_mlp1<<<N_GRAPHS / GT, 128>>>(fps, lw1, lb1, bn_g, bn_b, bn_rm, bn_rv);
    k_mlp2caps<<<N_GRAPHS, 128>>>(lw2, lb2, capsW, capsB, out);
}

// round 4
// speedup vs baseline: 2.7965x; 1.9203x over previous
#include <cuda_runtime.h>
#include <math.h>

#define N_NODES 200000
#define N_EDGES 800000
#define N_GRAPHS 8192
#define NFEAT 74
#define FPDIM 1024
#define HH 4
#define FF 50
#define HF 200
#define NT 16
#define GT 8

#define FMA_F32X2(d, a, b, c) \
    asm("fma.rn.f32x2 %0, %1, %2, %3;" : "=l"(d) : "l"(a), "l"(b), "l"(c))
#define DUP_F32X2(d, s) \
    asm("mov.b64 %0, {%1, %1};" : "=l"(d) : "f"(s))

// ---------------- scratch ----------------------------------------------------
__device__ float g_feat[N_NODES * HF];
__device__ float g_x1[N_NODES * HF];
__device__ float g_el[N_NODES * HH];
__device__ float g_er[N_NODES * HH];
__device__ float g_pool[N_GRAPHS * FF];
__device__ float g_z1[N_GRAPHS * 128];
__device__ int   g_deg[N_NODES];
__device__ int   g_cnt[N_NODES];
__device__ int   g_rowptr[N_NODES + 1];
__device__ int   g_csrc[N_EDGES];
__device__ int   g_bsum[256];
__device__ int   g_boff[256];

__device__ __forceinline__ float lrelu(float x, float s) { return x > 0.f ? x : s * x; }

__device__ __forceinline__ void atomicMaxF(float* addr, float v) {
    if (v >= 0.f) atomicMax((int*)addr, __float_as_int(v));
    else          atomicMin((unsigned int*)addr, __float_as_uint(v));
}

__device__ __forceinline__ float pickw(float4 a, int h) {
    return h == 0 ? a.x : (h == 1 ? a.y : (h == 2 ? a.z : a.w));
}

__global__ void k_fill(float* p, float v, int n) {
    int i = blockIdx.x * blockDim.x + threadIdx.x;
    if (i < n) p[i] = v;
}

// ---------------- CSR build --------------------------------------------------
__global__ void k_deg(const int* __restrict__ dst) {
    int e = blockIdx.x * blockDim.x + threadIdx.x;
    if (e < N_EDGES) atomicAdd(&g_deg[dst[e]], 1);
}

__global__ void k_scan1() {
    int i = blockIdx.x * 1024 + threadIdx.x;
    int v = (i < N_NODES) ? g_deg[i] : 0;
    int lane = threadIdx.x & 31, wid = threadIdx.x >> 5;
    int x = v;
#pragma unroll
    for (int o = 1; o < 32; o <<= 1) {
        int y = __shfl_up_sync(~0u, x, o);
        if (lane >= o) x += y;
    }
    __shared__ int ws[32];
    if (lane == 31) ws[wid] = x;
    __syncthreads();
    if (wid == 0) {
        int w = ws[lane];
#pragma unroll
        for (int o = 1; o < 32; o <<= 1) {
            int y = __shfl_up_sync(~0u, w, o);
            if (lane >= o) w += y;
        }
        ws[lane] = w;
    }
    __syncthreads();
    int incl = x + (wid > 0 ? ws[wid - 1] : 0);
    if (i < N_NODES) g_rowptr[i + 1] = incl;
    if (threadIdx.x == 1023) g_bsum[blockIdx.x] = incl;
}

__global__ void k_scan2(int nb) {
    int lane = threadIdx.x & 31, wid = threadIdx.x >> 5;
    int v = (threadIdx.x < nb) ? g_bsum[threadIdx.x] : 0;
    int x = v;
#pragma unroll
    for (int o = 1; o < 32; o <<= 1) {
        int y = __shfl_up_sync(~0u, x, o);
        if (lane >= o) x += y;
    }
    __shared__ int ws[8];
    if (lane == 31) ws[wid] = x;
    __syncthreads();
    if (threadIdx.x < 8) {
        int w = ws[threadIdx.x];
#pragma unroll
        for (int o = 1; o < 8; o <<= 1) {
            int y = __shfl_up_sync(0xffu, w, o);
            if ((threadIdx.x & 7) >= o) w += y;
        }
        ws[threadIdx.x] = w;
    }
    __syncthreads();
    int incl = x + (wid > 0 ? ws[wid - 1] : 0);
    g_boff[threadIdx.x] = incl - v;
}

__global__ void k_scan3() {
    int i = blockIdx.x * blockDim.x + threadIdx.x;
    if (i < N_NODES) g_rowptr[i + 1] += g_boff[i >> 10];
    if (i == 0) g_rowptr[0] = 0;
}

__global__ void k_scatter(const int* __restrict__ src, const int* __restrict__ dst) {
    int e = blockIdx.x * blockDim.x + threadIdx.x;
    if (e >= N_EDGES) return;
    int d = dst[e];
    int r = atomicAdd(&g_cnt[d], 1);
    g_csrc[g_rowptr[d] + r] = src[e];
}

// ------------- warp-segmented head reduction helper --------------------------
// warp covers <=2 heads (FF=50 > 32). Returns via atomics into sel/ser.
__device__ __forceinline__ void head_reduce(float vl, float vr, int hd, int hd0,
                                            int hd31, int lane, float* sel,
                                            float* ser, int rbase) {
    bool lo = (hd == hd0);
    float vll = lo ? vl : 0.f, vlh = lo ? 0.f : vl;
    float vrl = lo ? vr : 0.f, vrh = lo ? 0.f : vr;
#pragma unroll
    for (int o = 16; o; o >>= 1) {
        vll += __shfl_xor_sync(~0u, vll, o);
        vlh += __shfl_xor_sync(~0u, vlh, o);
        vrl += __shfl_xor_sync(~0u, vrl, o);
        vrh += __shfl_xor_sync(~0u, vrh, o);
    }
    if (lane == 0) {
        atomicAdd(&sel[rbase + hd0], vll);
        atomicAdd(&ser[rbase + hd0], vrl);
    }
    if (lane == 31 && hd31 != hd0) {
        atomicAdd(&sel[rbase + hd31], vlh);
        atomicAdd(&ser[rbase + hd31], vrh);
    }
}

// ---------------- layer-1 GEMM (f32x2): feat=h@W1, x1=h@resW1+b1, el/er ------
__global__ void __launch_bounds__(224) k_feat1(
        const float* __restrict__ h, const float* __restrict__ W1,
        const float* __restrict__ resW1, const float* __restrict__ al,
        const float* __restrict__ ar, const float* __restrict__ b1) {
    __shared__ __align__(16) float sxT[NFEAT * NT];
    __shared__ float sel[NT * HH], ser[NT * HH];
    int base = blockIdx.x * NT;
    int t = threadIdx.x;
    for (int i = t; i < NT * NFEAT; i += 224) {
        int r = i / NFEAT, k = i - r * NFEAT;
        sxT[k * NT + r] = h[(base + r) * NFEAT + k];
    }
    for (int i = t; i < NT * HH; i += 224) { sel[i] = 0.f; ser[i] = 0.f; }
    __syncthreads();
    int c = t;
    bool act = c < HF;
    int cc = act ? c : (HF - 1);
    union { unsigned long long u[NT / 2]; float f[NT]; } AF, AR;
#pragma unroll
    for (int q = 0; q < NT / 2; q++) { AF.u[q] = 0ull; AR.u[q] = 0ull; }
    if (act) {
#pragma unroll 2
        for (int k = 0; k < NFEAT; k++) {
            float w1v = W1[k * HF + c];
            float wrv = resW1[k * HF + c];
            unsigned long long wd1, wdr;
            DUP_F32X2(wd1, w1v);
            DUP_F32X2(wdr, wrv);
            const ulonglong2* xk = (const ulonglong2*)(sxT + k * NT);
#pragma unroll
            for (int q = 0; q < NT / 4; q++) {
                ulonglong2 xv = xk[q];
                FMA_F32X2(AF.u[2 * q + 0], xv.x, wd1, AF.u[2 * q + 0]);
                FMA_F32X2(AF.u[2 * q + 1], xv.y, wd1, AF.u[2 * q + 1]);
                FMA_F32X2(AR.u[2 * q + 0], xv.x, wdr, AR.u[2 * q + 0]);
                FMA_F32X2(AR.u[2 * q + 1], xv.y, wdr, AR.u[2 * q + 1]);
            }
        }
    }
    float alc = act ? al[c] : 0.f;
    float arc = act ? ar[c] : 0.f;
    float b1c = act ? b1[c] : 0.f;
    int hd = cc / FF;
    int lane = t & 31;
    int hd0 = __shfl_sync(~0u, hd, 0);
    int hd31 = __shfl_sync(~0u, hd, 31);
#pragma unroll
    for (int r = 0; r < NT; r++) {
        float fv = AF.f[r];
        if (act) {
            g_feat[(base + r) * HF + c] = fv;
            g_x1[(base + r) * HF + c] = AR.f[r] + b1c;
        }
        head_reduce(fv * alc, fv * arc, hd, hd0, hd31, lane, sel, ser, r * HH);
    }
    __syncthreads();
    for (int i = t; i < NT * HH; i += 224) {
        g_el[base * HH + i] = sel[i];
        g_er[base * HH + i] = ser[i];
    }
}

// ---------------- layer-2 GEMM (f32x2): feat=x1@W2, el/er --------------------
__global__ void __launch_bounds__(224) k_feat2(
        const float* __restrict__ W2, const float* __restrict__ al,
        const float* __restrict__ ar) {
    __shared__ __align__(16) float sxT[HF * NT];
    __shared__ float sel[NT * HH], ser[NT * HH];
    int base = blockIdx.x * NT;
    int t = threadIdx.x;
    for (int i = t; i < NT * HF; i += 224) {
        int r = i / HF, k = i - r * HF;
        sxT[k * NT + r] = g_x1[(base + r) * HF + k];
    }
    for (int i = t; i < NT * HH; i += 224) { sel[i] = 0.f; ser[i] = 0.f; }
    __syncthreads();
    int c = t;
    bool act = c < HF;
    int cc = act ? c : (HF - 1);
    union { unsigned long long u[NT / 2]; float f[NT]; } AF;
#pragma unroll
    for (int q = 0; q < NT / 2; q++) AF.u[q] = 0ull;
    if (act) {
#pragma unroll 2
        for (int k = 0; k < HF; k++) {
            float wv = W2[k * HF + c];
            unsigned long long wd;
            DUP_F32X2(wd, wv);
            const ulonglong2* xk = (const ulonglong2*)(sxT + k * NT);
#pragma unroll
            for (int q = 0; q < NT / 4; q++) {
                ulonglong2 xv = xk[q];
                FMA_F32X2(AF.u[2 * q + 0], xv.x, wd, AF.u[2 * q + 0]);
                FMA_F32X2(AF.u[2 * q + 1], xv.y, wd, AF.u[2 * q + 1]);
            }
        }
    }
    float alc = act ? al[c] : 0.f;
    float arc = act ? ar[c] : 0.f;
    int hd = cc / FF;
    int lane = t & 31;
    int hd0 = __shfl_sync(~0u, hd, 0);
    int hd31 = __shfl_sync(~0u, hd, 31);
#pragma unroll
    for (int r = 0; r < NT; r++) {
        float fv = AF.f[r];
        if (act) g_feat[(base + r) * HF + c] = fv;
        head_reduce(fv * alc, fv * arc, hd, hd0, hd31, lane, sel, ser, r * HH);
    }
    __syncthreads();
    for (int i = t; i < NT * HH; i += 224) {
        g_el[base * HH + i] = sel[i];
        g_er[base * HH + i] = ser[i];
    }
}

// ------- fused per-node softmax + aggregation + epilogue (warp per node) -----
template <int LAYER>
__global__ void __launch_bounds__(128) k_agg(const int* __restrict__ gid,
                                             const float* __restrict__ b2) {
    __shared__ float sm[4][HF];
    int w = threadIdx.x >> 5, lane = threadIdx.x & 31;
    int n = blockIdx.x * 4 + w;
    int beg = g_rowptr[n], deg = g_rowptr[n + 1] - beg;
    float4 er4 = *(const float4*)(g_er + n * 4);
    float4 m4 = make_float4(-INFINITY, -INFINITY, -INFINITY, -INFINITY);
    float4 dn4 = make_float4(0.f, 0.f, 0.f, 0.f);
    float i0 = 0.f, i1 = 0.f, i2 = 0.f, i3 = 0.f;
    if (deg > 0) {
        for (int j = lane; j < deg; j += 32) {
            int s = g_csrc[beg + j];
            float4 l4 = *(const float4*)(g_el + s * 4);
            m4.x = fmaxf(m4.x, lrelu(l4.x + er4.x, 0.2f));
            m4.y = fmaxf(m4.y, lrelu(l4.y + er4.y, 0.2f));
            m4.z = fmaxf(m4.z, lrelu(l4.z + er4.z, 0.2f));
            m4.w = fmaxf(m4.w, lrelu(l4.w + er4.w, 0.2f));
        }
#pragma unroll
        for (int o = 16; o; o >>= 1) {
            m4.x = fmaxf(m4.x, __shfl_xor_sync(~0u, m4.x, o));
            m4.y = fmaxf(m4.y, __shfl_xor_sync(~0u, m4.y, o));
            m4.z = fmaxf(m4.z, __shfl_xor_sync(~0u, m4.z, o));
            m4.w = fmaxf(m4.w, __shfl_xor_sync(~0u, m4.w, o));
        }
        for (int j = lane; j < deg; j += 32) {
            int s = g_csrc[beg + j];
            float4 l4 = *(const float4*)(g_el + s * 4);
            dn4.x += __expf(lrelu(l4.x + er4.x, 0.2f) - m4.x);
            dn4.y += __expf(lrelu(l4.y + er4.y, 0.2f) - m4.y);
            dn4.z += __expf(lrelu(l4.z + er4.z, 0.2f) - m4.z);
            dn4.w += __expf(lrelu(l4.w + er4.w, 0.2f) - m4.w);
        }
#pragma unroll
        for (int o = 16; o; o >>= 1) {
            dn4.x += __shfl_xor_sync(~0u, dn4.x, o);
            dn4.y += __shfl_xor_sync(~0u, dn4.y, o);
            dn4.z += __shfl_xor_sync(~0u, dn4.z, o);
            dn4.w += __shfl_xor_sync(~0u, dn4.w, o);
        }
        i0 = 1.f / dn4.x; i1 = 1.f / dn4.y; i2 = 1.f / dn4.z; i3 = 1.f / dn4.w;
    }
    int c0 = 4 * lane, c1 = 128 + 4 * lane;
    int h0l = c0 / FF, h0h = (c0 + 3) / FF, n0 = (h0l == h0h) ? 4 : (FF * h0h - c0);
    int h1l = c1 / FF, h1h = (c1 + 3) / FF, n1 = (h1l == h1h) ? 4 : (FF * h1h - c1);
    float4 acc0 = make_float4(0.f, 0.f, 0.f, 0.f);
    float4 acc1 = make_float4(0.f, 0.f, 0.f, 0.f);
    for (int j = 0; j < deg; j++) {
        int s = g_csrc[beg + j];
        float4 l4 = *(const float4*)(g_el + s * 4);
        float4 aj;
        aj.x = __expf(lrelu(l4.x + er4.x, 0.2f) - m4.x) * i0;
        aj.y = __expf(lrelu(l4.y + er4.y, 0.2f) - m4.y) * i1;
        aj.z = __expf(lrelu(l4.z + er4.z, 0.2f) - m4.z) * i2;
        aj.w = __expf(lrelu(l4.w + er4.w, 0.2f) - m4.w) * i3;
        const float4* fr = (const float4*)(g_feat + s * HF);
        float4 f0 = fr[lane];
        float wl = pickw(aj, h0l), wh = pickw(aj, h0h);
        acc0.x = fmaf((0 < n0 ? wl : wh), f0.x, acc0.x);
        acc0.y = fmaf((1 < n0 ? wl : wh), f0.y, acc0.y);
        acc0.z = fmaf((2 < n0 ? wl : wh), f0.z, acc0.z);
        acc0.w = fmaf((3 < n0 ? wl : wh), f0.w, acc0.w);
        if (lane < 18) {
            float4 f1 = fr[32 + lane];
            float wl1 = pickw(aj, h1l), wh1 = pickw(aj, h1h);
            acc1.x = fmaf((0 < n1 ? wl1 : wh1), f1.x, acc1.x);
            acc1.y = fmaf((1 < n1 ? wl1 : wh1), f1.y, acc1.y);
            acc1.z = fmaf((2 < n1 ? wl1 : wh1), f1.z, acc1.z);
            acc1.w = fmaf((3 < n1 ? wl1 : wh1), f1.w, acc1.w);
        }
    }
    float4* xrow = (float4*)(g_x1 + n * HF);
    if (LAYER == 1) {
        float4 r0 = xrow[lane];
        r0.x = lrelu(acc0.x + r0.x, 0.01f);
        r0.y = lrelu(acc0.y + r0.y, 0.01f);
        r0.z = lrelu(acc0.z + r0.z, 0.01f);
        r0.w = lrelu(acc0.w + r0.w, 0.01f);
        xrow[lane] = r0;
        if (lane < 18) {
            float4 r1 = xrow[32 + lane];
            r1.x = lrelu(acc1.x + r1.x, 0.01f);
            r1.y = lrelu(acc1.y + r1.y, 0.01f);
            r1.z = lrelu(acc1.z + r1.z, 0.01f);
            r1.w = lrelu(acc1.w + r1.w, 0.01f);
            xrow[32 + lane] = r1;
        }
    } else {
        float4 r0 = xrow[lane];
        float4 bb0 = *(const float4*)(b2 + c0);
        sm[w][c0 + 0] = acc0.x + r0.x + bb0.x;
        sm[w][c0 + 1] = acc0.y + r0.y + bb0.y;
        sm[w][c0 + 2] = acc0.z + r0.z + bb0.z;
        sm[w][c0 + 3] = acc0.w + r0.w + bb0.w;
        if (lane < 18) {
            float4 r1 = xrow[32 + lane];
            float4 bb1 = *(const float4*)(b2 + c1);
            sm[w][c1 + 0] = acc1.x + r1.x + bb1.x;
            sm[w][c1 + 1] = acc1.y + r1.y + bb1.y;
            sm[w][c1 + 2] = acc1.z + r1.z + bb1.z;
            sm[w][c1 + 3] = acc1.w + r1.w + bb1.w;
        }
        __syncwarp();
        int g = gid[n];
        {
            int f = lane;
            float v = 0.25f * (sm[w][f] + sm[w][f + FF] + sm[w][f + 2 * FF] + sm[w][f + 3 * FF]);
            atomicMaxF(&g_pool[g * FF + f], v);
        }
        if (lane < 18) {
            int f = 32 + lane;
            float v = 0.25f * (sm[w][f] + sm[w][f + FF] + sm[w][f + 2 * FF] + sm[w][f + 3 * FF]);
            atomicMaxF(&g_pool[g * FF + f], v);
        }
    }
}

// ---------------- MLP layer 1 + BN (f32x2, transposed smem) ------------------
__global__ void k_mlp1(const float* __restrict__ fps, const float* __restrict__ lw1,
                       const float* __restrict__ lb1, const float* __restrict__ bn_g,
                       const float* __restrict__ bn_b, const float* __restrict__ bn_rm,
                       const float* __restrict__ bn_rv) {
    __shared__ __align__(16) float szT[1074 * GT];
    int gb = blockIdx.x * GT;
    for (int i = threadIdx.x; i < GT * FF; i += blockDim.x) {
        int r = i / FF, k = i % FF;
        szT[k * GT + r] = g_pool[(gb + r) * FF + k];
    }
    for (int i = threadIdx.x; i < GT * FPDIM; i += blockDim.x) {
        int r = i / FPDIM, k = i % FPDIM;
        szT[(FF + k) * GT + r] = fps[(gb + r) * FPDIM + k];
    }
    __syncthreads();
    int c = threadIdx.x;
    union { unsigned long long u[GT / 2]; float f[GT]; } A;
#pragma unroll
    for (int q = 0; q < GT / 2; q++) A.u[q] = 0ull;
    for (int k = 0; k < 1074; k++) {
        float w = lw1[k * 128 + c];
        unsigned long long wd;
        DUP_F32X2(wd, w);
        const ulonglong2* zk = (const ulonglong2*)(szT + k * GT);
        ulonglong2 z0 = zk[0], z1 = zk[1];
        FMA_F32X2(A.u[0], z0.x, wd, A.u[0]);
        FMA_F32X2(A.u[1], z0.y, wd, A.u[1]);
        FMA_F32X2(A.u[2], z1.x, wd, A.u[2]);
        FMA_F32X2(A.u[3], z1.y, wd, A.u[3]);
    }
    float lb = lb1[c];
    float mu = bn_rm[c];
    float scl = rsqrtf(bn_rv[c] + 1e-5f) * bn_g[c];
    float bb = bn_b[c];
#pragma unroll
    for (int r = 0; r < GT; r++) {
        float z = fmaxf(A.f[r] + lb, 0.f);
        g_z1[(gb + r) * 128 + c] = (z - mu) * scl + bb;
    }
}

// ---------------- MLP layer 2 + capsule head ---------------------------------
__global__ void k_mlp2caps(const float* __restrict__ lw2, const float* __restrict__ lb2,
                           const float* __restrict__ capsW, const float* __restrict__ capsB,
                           float* __restrict__ out) {
    __shared__ float sz1[128];
    __shared__ float sz2[128];
    __shared__ float su[16 * 8];
    __shared__ float suh[2 * 16 * 2];
    __shared__ float sUS[4];
    __shared__ float sas[2 * 16];
    __shared__ float scx[2 * 16];
    __shared__ float ss[4];
    int g = blockIdx.x;
    int t = threadIdx.x;
    sz1[t] = g_z1[g * 128 + t];
    __syncthreads();
    float acc = lb2[t];
#pragma unroll 8
    for (int k = 0; k < 128; k++) acc = fmaf(sz1[k], lw2[k * 128 + t], acc);
    sz2[t] = fmaxf(acc, 0.f);
    __syncthreads();
    if (t < 16) {
        float sq = 0.f;
#pragma unroll
        for (int e = 0; e < 8; e++) { float v = sz2[t * 8 + e]; sq += v * v; }
        float rt = sqrtf(sq);
        float f = (1.f - __expf(-rt)) / sqrtf(sq + 1e-8f);
#pragma unroll
        for (int e = 0; e < 8; e++) su[t * 8 + e] = f * sz2[t * 8 + e];
    }
    __syncthreads();
    if (t < 64) {
        int n = t >> 5, rem = t & 31, c = rem >> 1, d = rem & 1;
        const float* w = capsW + ((n * 16 + c) * 2 + d) * 8;
        float s = 0.f;
#pragma unroll
        for (int e = 0; e < 8; e++) s = fmaf(w[e], su[c * 8 + e], s);
        suh[(n * 16 + c) * 2 + d] = s;
    }
    __syncthreads();
    if (t < 4) {
        int n = t >> 1, d = t & 1;
        float s = 0.f;
        for (int c = 0; c < 16; c++) s += suh[(n * 16 + c) * 2 + d];
        sUS[t] = s;
    }
    __syncthreads();
    if (t < 32) {
        int n = t >> 4, k = t & 15;
        sas[t] = 0.08838834764831845f *
                 (sUS[n * 2 + 0] * suh[(n * 16 + k) * 2 + 0] +
                  sUS[n * 2 + 1] * suh[(n * 16 + k) * 2 + 1]);
    }
    __syncthreads();
    if (t < 16) {
        float a0 = sas[t], a1 = sas[16 + t];
        float m = fmaxf(a0, a1);
        float e0 = __expf(a0 - m), e1 = __expf(a1 - m);
        float inv = 1.f / (e0 + e1);
        scx[t] = e0 * inv;
        scx[16 + t] = e1 * inv;
    }
    __syncthreads();
    if (t < 4) {
        int n = t >> 1, d = t & 1;
        float s = 0.f;
        for (int k = 0; k < 16; k++)
            s = fmaf(scx[n * 16 + k] + capsB[n * 16 + k], suh[(n * 16 + k) * 2 + d], s);
        ss[n * 2 + d] = s;
    }
    __syncthreads();
    if (t < 2) {
        float s0 = ss[t * 2 + 0], s1 = ss[t * 2 + 1];
        float sq = s0 * s0 + s1 * s1;
        float rt = sqrtf(sq);
        float f = (1.f - __expf(-rt)) / sqrtf(sq + 1e-8f);
        float v0 = f * s0, v1 = f * s1;
        out[g * 2 + t] = sqrtf(v0 * v0 + v1 * v1 + 1e-8f);
    }
}

// ---------------- launcher ---------------------------------------------------
extern "C" void kernel_launch(void* const* d_in, const int* in_sizes, int n_in,
                              void* d_out, int out_size) {
    const float* h     = (const float*)d_in[0];
    const float* fps   = (const float*)d_in[1];
    const int*   src   = (const int*)d_in[2];
    const int*   dst   = (const int*)d_in[3];
    const int*   gid   = (const int*)d_in[4];
    const float* W1    = (const float*)d_in[5];
    const float* al1   = (const float*)d_in[6];
    const float* ar1   = (const float*)d_in[7];
    const float* b1    = (const float*)d_in[8];
    const float* resW1 = (const float*)d_in[9];
    const float* W2    = (const float*)d_in[10];
    const float* al2   = (const float*)d_in[11];
    const float* ar2   = (const float*)d_in[12];
    const float* b2    = (const float*)d_in[13];
    const float* lw1   = (const float*)d_in[14];
    const float* lb1   = (const float*)d_in[15];
    const float* bn_g  = (const float*)d_in[16];
    const float* bn_b  = (const float*)d_in[17];
    const float* bn_rm = (const float*)d_in[18];
    const float* bn_rv = (const float*)d_in[19];
    const float* lw2   = (const float*)d_in[20];
    const float* lb2   = (const float*)d_in[21];
    const float* capsW = (const float*)d_in[22];
    const float* capsB = (const float*)d_in[23];
    float* out = (float*)d_out;

    float *p_deg, *p_cnt, *p_pool;
    cudaGetSymbolAddress((void**)&p_deg, g_deg);
    cudaGetSymbolAddress((void**)&p_cnt, g_cnt);
    cudaGetSymbolAddress((void**)&p_pool, g_pool);

    const int NB_E = (N_EDGES + 255) / 256;
    const int NB_N = (N_NODES + 255) / 256;
    const int NB_SCAN = (N_NODES + 1023) / 1024;

    // ---- CSR build ----
    k_fill<<<NB_N, 256>>>(p_deg, 0.f, N_NODES);
    k_fill<<<NB_N, 256>>>(p_cnt, 0.f, N_NODES);
    k_fill<<<(N_GRAPHS * FF + 255) / 256, 256>>>(p_pool, -INFINITY, N_GRAPHS * FF);
    k_deg<<<NB_E, 256>>>(dst);
    k_scan1<<<NB_SCAN, 1024>>>();
    k_scan2<<<1, 256>>>(NB_SCAN);
    k_scan3<<<NB_N, 256>>>();
    k_scatter<<<NB_E, 256>>>(src, dst);

    // ---- GAT layer 1 ----
    k_feat1<<<N_NODES / NT, 224>>>(h, W1, resW1, al1, ar1, b1);
    k_agg<1><<<N_NODES / 4, 128>>>(gid, b2);

    // ---- GAT layer 2 ----
    k_feat2<<<N_NODES / NT, 224>>>(W2, al2, ar2);
    k_agg<2><<<N_NODES / 4, 128>>>(gid, b2);

    // ---- MLP + caps ----
    k_mlp1<<<N_GRAPHS / GT, 128>>>(fps, lw1, lb1, bn_g, bn_b, bn_rm, bn_rv);
    k_mlp2caps<<<N_GRAPHS, 128>>>(lw2, lb2, capsW, capsB, out);
}